// round 14
// baseline (speedup 1.0000x reference)
#include <cuda_runtime.h>
#include <cuda_fp16.h>
#include <cstdint>

#define N_NODES 100000
#define N_EDGES 1600000
#define SCAN_BS 1024
#define SCAN_NB ((N_NODES + SCAN_BS - 1) / SCAN_BS)   // 98

// Ping-pong node-feature buffers. bufA holds f32 D=32 (layer1) then f16 D=64
// (layer2 intermediate); bufB holds f16 D=64 (post-relu layer1 output).
__device__ float g_bufA[(size_t)N_NODES * 64];
__device__ float g_bufB[(size_t)N_NODES * 64];

// CSR scratch (graph identical across all 4 SpMMs -> build once per launch).
__device__ int    g_deg[N_NODES];
__device__ int    g_rowstart[N_NODES + 1];
__device__ int    g_cursor[N_NODES];
__device__ int    g_bsums[128];
__device__ float2 g_epack[N_EDGES];   // {.x = __int_as_float(col), .y = 0.5f*val}

// ---------------------------------------------------------------------------
// CSR build
// ---------------------------------------------------------------------------
__global__ void zero_deg_kernel() {
    int i = blockIdx.x * blockDim.x + threadIdx.x;
    if (i < N_NODES) g_deg[i] = 0;
}

__global__ void hist_kernel(const int* __restrict__ erow) {
    int i = blockIdx.x * blockDim.x + threadIdx.x;
    if (i < N_EDGES) atomicAdd(&g_deg[erow[i]], 1);
}

__global__ void scan_local_kernel() {
    __shared__ int s[SCAN_BS];
    int tid = threadIdx.x;
    int idx = blockIdx.x * SCAN_BS + tid;
    int v = (idx < N_NODES) ? g_deg[idx] : 0;
    s[tid] = v;
    __syncthreads();
#pragma unroll
    for (int off = 1; off < SCAN_BS; off <<= 1) {
        int t = (tid >= off) ? s[tid - off] : 0;
        __syncthreads();
        s[tid] += t;
        __syncthreads();
    }
    if (idx < N_NODES) g_rowstart[idx] = s[tid] - v;   // exclusive
    if (tid == SCAN_BS - 1) g_bsums[blockIdx.x] = s[tid];
}

__global__ void scan_add_kernel() {
    __shared__ int sb[128];
    int tid = threadIdx.x;   // 256 threads
    if (tid < 128) sb[tid] = (tid < SCAN_NB) ? g_bsums[tid] : 0;
    __syncthreads();
#pragma unroll
    for (int off = 1; off < 128; off <<= 1) {
        int t = (tid < 128 && tid >= off) ? sb[tid - off] : 0;
        __syncthreads();
        if (tid < 128) sb[tid] += t;
        __syncthreads();
    }
    int idx = blockIdx.x * blockDim.x + tid;
    if (idx < N_NODES) {
        int blk = idx >> 10;
        int add = (blk == 0) ? 0 : sb[blk - 1];
        int r = g_rowstart[idx] + add;
        g_rowstart[idx] = r;
        g_cursor[idx] = r;
    }
    if (idx == 0) g_rowstart[N_NODES] = N_EDGES;
}

__global__ void scatter_edges_kernel(const int* __restrict__ erow,
                                     const int* __restrict__ ecol,
                                     const float* __restrict__ eval) {
    int i = blockIdx.x * blockDim.x + threadIdx.x;
    if (i >= N_EDGES) return;
    int r = erow[i];
    int p = atomicAdd(&g_cursor[r], 1);
    float2 pk;
    pk.x = __int_as_float(ecol[i]);
    pk.y = 0.5f * eval[i];
    g_epack[p] = pk;
}

// ---------------------------------------------------------------------------
// f32 warp-level row reduce, D=32: C=8 f4-chunks, SUBS=4 edge lanes.
// Unrolled x4: 4 independent accumulators, all 4 epack loads then all 4
// gathers issued before any FMA consumes them (MLP=4 per lane).
// ---------------------------------------------------------------------------
__device__ __forceinline__ float4 row_reduce32f(const float4* __restrict__ src,
                                                int row, int sub, int c) {
    constexpr int SUBS = 4;
    int start = g_rowstart[row];
    int end   = g_rowstart[row + 1];

    float4 a0 = make_float4(0.f, 0.f, 0.f, 0.f);
    float4 a1 = a0, a2 = a0, a3 = a0;
    int e = start + sub;
    for (; e + 3 * SUBS < end; e += 4 * SUBS) {
        float2 ev0 = __ldg(&g_epack[e]);
        float2 ev1 = __ldg(&g_epack[e + SUBS]);
        float2 ev2 = __ldg(&g_epack[e + 2 * SUBS]);
        float2 ev3 = __ldg(&g_epack[e + 3 * SUBS]);
        float4 g0 = __ldg(&src[(size_t)__float_as_int(ev0.x) * 8 + c]);
        float4 g1 = __ldg(&src[(size_t)__float_as_int(ev1.x) * 8 + c]);
        float4 g2 = __ldg(&src[(size_t)__float_as_int(ev2.x) * 8 + c]);
        float4 g3 = __ldg(&src[(size_t)__float_as_int(ev3.x) * 8 + c]);
        a0.x = fmaf(ev0.y, g0.x, a0.x); a0.y = fmaf(ev0.y, g0.y, a0.y);
        a0.z = fmaf(ev0.y, g0.z, a0.z); a0.w = fmaf(ev0.y, g0.w, a0.w);
        a1.x = fmaf(ev1.y, g1.x, a1.x); a1.y = fmaf(ev1.y, g1.y, a1.y);
        a1.z = fmaf(ev1.y, g1.z, a1.z); a1.w = fmaf(ev1.y, g1.w, a1.w);
        a2.x = fmaf(ev2.y, g2.x, a2.x); a2.y = fmaf(ev2.y, g2.y, a2.y);
        a2.z = fmaf(ev2.y, g2.z, a2.z); a2.w = fmaf(ev2.y, g2.w, a2.w);
        a3.x = fmaf(ev3.y, g3.x, a3.x); a3.y = fmaf(ev3.y, g3.y, a3.y);
        a3.z = fmaf(ev3.y, g3.z, a3.z); a3.w = fmaf(ev3.y, g3.w, a3.w);
    }
    for (; e < end; e += SUBS) {
        float2 ev = __ldg(&g_epack[e]);
        float4 g = __ldg(&src[(size_t)__float_as_int(ev.x) * 8 + c]);
        a0.x = fmaf(ev.y, g.x, a0.x); a0.y = fmaf(ev.y, g.y, a0.y);
        a0.z = fmaf(ev.y, g.z, a0.z); a0.w = fmaf(ev.y, g.w, a0.w);
    }
    a0.x += a1.x + a2.x + a3.x;
    a0.y += a1.y + a2.y + a3.y;
    a0.z += a1.z + a2.z + a3.z;
    a0.w += a1.w + a2.w + a3.w;

#pragma unroll
    for (int off = 8; off < 32; off <<= 1) {
        a0.x += __shfl_xor_sync(0xFFFFFFFFu, a0.x, off);
        a0.y += __shfl_xor_sync(0xFFFFFFFFu, a0.y, off);
        a0.z += __shfl_xor_sync(0xFFFFFFFFu, a0.z, off);
        a0.w += __shfl_xor_sync(0xFFFFFFFFu, a0.w, off);
    }
    return a0;
}

// ---------------------------------------------------------------------------
// f16 fma helper: g = 8 packed halfs; accumulate v*g into lo/hi float4.
// ---------------------------------------------------------------------------
__device__ __forceinline__ void fma8h(float4 g, float v, float4& lo, float4& hi) {
    const __half2* h = reinterpret_cast<const __half2*>(&g);
    float2 p;
    p = __half22float2(h[0]); lo.x = fmaf(v, p.x, lo.x); lo.y = fmaf(v, p.y, lo.y);
    p = __half22float2(h[1]); lo.z = fmaf(v, p.x, lo.z); lo.w = fmaf(v, p.y, lo.w);
    p = __half22float2(h[2]); hi.x = fmaf(v, p.x, hi.x); hi.y = fmaf(v, p.y, hi.y);
    p = __half22float2(h[3]); hi.z = fmaf(v, p.x, hi.z); hi.w = fmaf(v, p.y, hi.w);
}

// ---------------------------------------------------------------------------
// f16 warp-level row reduce, D=64: C=8 f4-chunks, SUBS=4. Unrolled x4:
// two accumulator pairs, 4 loads in flight (a0 takes ev0/ev2, a1 takes ev1/ev3).
// ---------------------------------------------------------------------------
__device__ __forceinline__ void row_reduce64h(const float4* __restrict__ src,
                                              int row, int sub, int c,
                                              float4& lo_out, float4& hi_out) {
    constexpr int SUBS = 4;
    int start = g_rowstart[row];
    int end   = g_rowstart[row + 1];

    float4 l0 = make_float4(0.f, 0.f, 0.f, 0.f), h0 = l0;
    float4 l1 = l0, h1 = l0;
    int e = start + sub;
    for (; e + 3 * SUBS < end; e += 4 * SUBS) {
        float2 ev0 = __ldg(&g_epack[e]);
        float2 ev1 = __ldg(&g_epack[e + SUBS]);
        float2 ev2 = __ldg(&g_epack[e + 2 * SUBS]);
        float2 ev3 = __ldg(&g_epack[e + 3 * SUBS]);
        float4 g0 = __ldg(&src[(size_t)__float_as_int(ev0.x) * 8 + c]);
        float4 g1 = __ldg(&src[(size_t)__float_as_int(ev1.x) * 8 + c]);
        float4 g2 = __ldg(&src[(size_t)__float_as_int(ev2.x) * 8 + c]);
        float4 g3 = __ldg(&src[(size_t)__float_as_int(ev3.x) * 8 + c]);
        fma8h(g0, ev0.y, l0, h0);
        fma8h(g1, ev1.y, l1, h1);
        fma8h(g2, ev2.y, l0, h0);
        fma8h(g3, ev3.y, l1, h1);
    }
    for (; e < end; e += SUBS) {
        float2 ev = __ldg(&g_epack[e]);
        float4 g = __ldg(&src[(size_t)__float_as_int(ev.x) * 8 + c]);
        fma8h(g, ev.y, l0, h0);
    }
    l0.x += l1.x; l0.y += l1.y; l0.z += l1.z; l0.w += l1.w;
    h0.x += h1.x; h0.y += h1.y; h0.z += h1.z; h0.w += h1.w;

#pragma unroll
    for (int off = 8; off < 32; off <<= 1) {
        l0.x += __shfl_xor_sync(0xFFFFFFFFu, l0.x, off);
        l0.y += __shfl_xor_sync(0xFFFFFFFFu, l0.y, off);
        l0.z += __shfl_xor_sync(0xFFFFFFFFu, l0.z, off);
        l0.w += __shfl_xor_sync(0xFFFFFFFFu, l0.w, off);
        h0.x += __shfl_xor_sync(0xFFFFFFFFu, h0.x, off);
        h0.y += __shfl_xor_sync(0xFFFFFFFFu, h0.y, off);
        h0.z += __shfl_xor_sync(0xFFFFFFFFu, h0.z, off);
        h0.w += __shfl_xor_sync(0xFFFFFFFFu, h0.w, off);
    }
    lo_out = l0; hi_out = h0;
}

// ---------------------------------------------------------------------------
// Pass 1: SpMM D=32 f32, x -> bufA. One warp per row.
// ---------------------------------------------------------------------------
__global__ void spmm_gather32_kernel(const float* __restrict__ x) {
    const float4* __restrict__ src = reinterpret_cast<const float4*>(x);
    float4* dst = reinterpret_cast<float4*>(g_bufA);

    int warp_id = (blockIdx.x * blockDim.x + threadIdx.x) >> 5;
    if (warp_id >= N_NODES) return;
    int lane = threadIdx.x & 31;
    int sub = lane >> 3, c = lane & 7;

    float4 acc = row_reduce32f(src, warp_id, sub, c);
    if (sub == 0) dst[(size_t)warp_id * 8 + c] = acc;
}

// ---------------------------------------------------------------------------
// Pass 2: fused SpMM(D=32 f32, bufA) + linear(32->64) + relu -> bufB (f16).
// 256 threads = 8 warps = 8 rows; warp-private srow + __syncwarp.
// ---------------------------------------------------------------------------
__global__ void spmm_linear32_kernel(const float* __restrict__ W,
                                     const float* __restrict__ b) {
    constexpr int WARPS = 8;
    __shared__ __align__(16) float sW[32][64];
    __shared__ __align__(16) float sbias[64];
    __shared__ __align__(16) float srow[WARPS][32];

    const float4* __restrict__ src = reinterpret_cast<const float4*>(g_bufA);
    __half2* dst = reinterpret_cast<__half2*>(g_bufB);

    int tid = threadIdx.x;
    for (int k = tid; k < 32 * 64; k += 256) sW[k >> 6][k & 63] = W[k];
    if (tid < 64) sbias[tid] = b[tid];
    __syncthreads();

    int warp = tid >> 5, lane = tid & 31;
    int row = blockIdx.x * WARPS + warp;   // 100000 = 12500 * 8, exact
    int sub = lane >> 3, c = lane & 7;

    float4 acc = row_reduce32f(src, row, sub, c);
    if (sub == 0) reinterpret_cast<float4*>(srow[warp])[c] = acc;
    __syncwarp();

    const float2* sW2 = reinterpret_cast<const float2*>(&sW[0][0]);
    float2 o = reinterpret_cast<const float2*>(sbias)[lane];
#pragma unroll
    for (int k = 0; k < 32; k++) {
        float r = srow[warp][k];
        float2 w = sW2[k * 32 + lane];
        o.x = fmaf(r, w.x, o.x);
        o.y = fmaf(r, w.y, o.y);
    }
    o.x = fmaxf(o.x, 0.f);
    o.y = fmaxf(o.y, 0.f);
    dst[(size_t)row * 32 + lane] = __floats2half2_rn(o.x, o.y);
}

// ---------------------------------------------------------------------------
// Pass 3: SpMM D=64 f16, bufB -> bufA (f16). One warp per row, SUBS=4.
// ---------------------------------------------------------------------------
__global__ void spmm_gather64h_kernel() {
    const float4* __restrict__ src = reinterpret_cast<const float4*>(g_bufB);
    float4* dst = reinterpret_cast<float4*>(g_bufA);

    int warp_id = (blockIdx.x * blockDim.x + threadIdx.x) >> 5;
    if (warp_id >= N_NODES) return;
    int lane = threadIdx.x & 31;
    int sub = lane >> 3, c = lane & 7;

    float4 lo, hi;
    row_reduce64h(src, warp_id, sub, c, lo, hi);
    if (sub == 0) {
        float4 pk;
        __half2* p = reinterpret_cast<__half2*>(&pk);
        p[0] = __floats2half2_rn(lo.x, lo.y);
        p[1] = __floats2half2_rn(lo.z, lo.w);
        p[2] = __floats2half2_rn(hi.x, hi.y);
        p[3] = __floats2half2_rn(hi.z, hi.w);
        dst[(size_t)warp_id * 8 + c] = pk;
    }
}

// ---------------------------------------------------------------------------
// Pass 4: fused SpMM(D=64 f16, bufA) + linear(64->64) + bias -> out (f32).
// ---------------------------------------------------------------------------
__global__ void spmm_linear64h_kernel(float* __restrict__ out,
                                      const float* __restrict__ W,
                                      const float* __restrict__ b) {
    constexpr int WARPS = 8;
    __shared__ __align__(16) float sW[64][64];
    __shared__ __align__(16) float sbias[64];
    __shared__ __align__(16) float srow[WARPS][64];

    const float4* __restrict__ src = reinterpret_cast<const float4*>(g_bufA);

    int tid = threadIdx.x;
    for (int k = tid; k < 64 * 64; k += 256) sW[k >> 6][k & 63] = W[k];
    if (tid < 64) sbias[tid] = b[tid];
    __syncthreads();

    int warp = tid >> 5, lane = tid & 31;
    int row = blockIdx.x * WARPS + warp;   // exact
    int sub = lane >> 3, c = lane & 7;

    float4 lo, hi;
    row_reduce64h(src, row, sub, c, lo, hi);
    if (sub == 0) {
        float4* s4 = reinterpret_cast<float4*>(srow[warp]);
        s4[2 * c]     = lo;   // cols 8c .. 8c+3
        s4[2 * c + 1] = hi;   // cols 8c+4 .. 8c+7
    }
    __syncwarp();

    const float2* sW2 = reinterpret_cast<const float2*>(&sW[0][0]);
    float2 o = reinterpret_cast<const float2*>(sbias)[lane];
#pragma unroll
    for (int k = 0; k < 64; k++) {
        float r = srow[warp][k];
        float2 w = sW2[k * 32 + lane];
        o.x = fmaf(r, w.x, o.x);
        o.y = fmaf(r, w.y, o.y);
    }
    reinterpret_cast<float2*>(out)[(size_t)row * 32 + lane] = o;
}

// ---------------------------------------------------------------------------
// Launch sequence:
//   CSR build (5 kernels, shared by all 4 propagations)
//   bufA(f32,32) <- spmm(x)
//   bufB(f16,64) <- relu(spmm(bufA) @ W1 + b1)     (fused)
//   bufA(f16,64) <- spmm(bufB)
//   out(f32)     <- spmm(bufA) @ W2 + b2           (fused)
// ---------------------------------------------------------------------------
extern "C" void kernel_launch(void* const* d_in, const int* in_sizes, int n_in,
                              void* d_out, int out_size) {
    const float* x    = (const float*)d_in[0];
    const float* evl  = (const float*)d_in[1];
    const int*   erow = (const int*)  d_in[2];
    const int*   ecol = (const int*)  d_in[3];
    const float* W1   = (const float*)d_in[4];
    const float* b1   = (const float*)d_in[5];
    const float* W2   = (const float*)d_in[6];
    const float* b2   = (const float*)d_in[7];
    float* out = (float*)d_out;

    const int TPB = 256;
    int node_blocks = (N_NODES + TPB - 1) / TPB;
    int edge_blocks = (N_EDGES + TPB - 1) / TPB;
    int warp_blocks = (N_NODES * 32 + TPB - 1) / TPB;   // 12500
    int fused_blocks = N_NODES / 8;                      // 12500

    // --- CSR build ---
    zero_deg_kernel<<<node_blocks, TPB>>>();
    hist_kernel<<<edge_blocks, TPB>>>(erow);
    scan_local_kernel<<<SCAN_NB, SCAN_BS>>>();
    scan_add_kernel<<<node_blocks, TPB>>>();
    scatter_edges_kernel<<<edge_blocks, TPB>>>(erow, ecol, evl);

    // --- layer 1 ---
    spmm_gather32_kernel<<<warp_blocks, TPB>>>(x);
    spmm_linear32_kernel<<<fused_blocks, TPB>>>(W1, b1);

    // --- layer 2 (f16 features) ---
    spmm_gather64h_kernel<<<warp_blocks, TPB>>>();
    spmm_linear64h_kernel<<<fused_blocks, TPB>>>(out, W2, b2);
}

// round 15
// speedup vs baseline: 1.0536x; 1.0536x over previous
#include <cuda_runtime.h>
#include <cuda_fp16.h>
#include <cstdint>

#define N_NODES 100000
#define N_EDGES 1600000
#define SCAN_BS 1024
#define SCAN_NB ((N_NODES + SCAN_BS - 1) / SCAN_BS)   // 98
#define CHUNK 64   // edges staged per warp round

// Ping-pong node-feature buffers. bufA holds f32 D=32 (layer1) then f16 D=64
// (layer2 intermediate); bufB holds f16 D=64 (post-relu layer1 output).
__device__ float g_bufA[(size_t)N_NODES * 64];
__device__ float g_bufB[(size_t)N_NODES * 64];

// CSR scratch (graph identical across all 4 SpMMs -> build once per launch).
__device__ int    g_deg[N_NODES];
__device__ int    g_rowstart[N_NODES + 1];
__device__ int    g_cursor[N_NODES];
__device__ int    g_bsums[128];
__device__ float2 g_epack[N_EDGES];   // {.x = __int_as_float(col), .y = 0.5f*val}

// ---------------------------------------------------------------------------
// CSR build
// ---------------------------------------------------------------------------
__global__ void zero_deg_kernel() {
    int i = blockIdx.x * blockDim.x + threadIdx.x;
    if (i < N_NODES) g_deg[i] = 0;
}

__global__ void hist_kernel(const int* __restrict__ erow) {
    int i = blockIdx.x * blockDim.x + threadIdx.x;
    if (i < N_EDGES) atomicAdd(&g_deg[erow[i]], 1);
}

__global__ void scan_local_kernel() {
    __shared__ int s[SCAN_BS];
    int tid = threadIdx.x;
    int idx = blockIdx.x * SCAN_BS + tid;
    int v = (idx < N_NODES) ? g_deg[idx] : 0;
    s[tid] = v;
    __syncthreads();
#pragma unroll
    for (int off = 1; off < SCAN_BS; off <<= 1) {
        int t = (tid >= off) ? s[tid - off] : 0;
        __syncthreads();
        s[tid] += t;
        __syncthreads();
    }
    if (idx < N_NODES) g_rowstart[idx] = s[tid] - v;   // exclusive
    if (tid == SCAN_BS - 1) g_bsums[blockIdx.x] = s[tid];
}

__global__ void scan_add_kernel() {
    __shared__ int sb[128];
    int tid = threadIdx.x;   // 256 threads
    if (tid < 128) sb[tid] = (tid < SCAN_NB) ? g_bsums[tid] : 0;
    __syncthreads();
#pragma unroll
    for (int off = 1; off < 128; off <<= 1) {
        int t = (tid < 128 && tid >= off) ? sb[tid - off] : 0;
        __syncthreads();
        if (tid < 128) sb[tid] += t;
        __syncthreads();
    }
    int idx = blockIdx.x * blockDim.x + tid;
    if (idx < N_NODES) {
        int blk = idx >> 10;
        int add = (blk == 0) ? 0 : sb[blk - 1];
        int r = g_rowstart[idx] + add;
        g_rowstart[idx] = r;
        g_cursor[idx] = r;
    }
    if (idx == 0) g_rowstart[N_NODES] = N_EDGES;
}

__global__ void scatter_edges_kernel(const int* __restrict__ erow,
                                     const int* __restrict__ ecol,
                                     const float* __restrict__ eval) {
    int i = blockIdx.x * blockDim.x + threadIdx.x;
    if (i >= N_EDGES) return;
    int r = erow[i];
    int p = atomicAdd(&g_cursor[r], 1);
    float2 pk;
    pk.x = __int_as_float(ecol[i]);
    pk.y = 0.5f * eval[i];
    g_epack[p] = pk;
}

// ---------------------------------------------------------------------------
// Staged f32 warp row reduce, D=32: C=8 f4-chunks, SUBS=4 edge lanes.
// Edge list staged through smem (coalesced 32-lane loads), then the gather
// loop reads edges from smem (29cyc) -> LDGs batch at LSU rate.
// ---------------------------------------------------------------------------
__device__ __forceinline__ float4 row_reduce32f(const float4* __restrict__ src,
                                                float2* __restrict__ se,
                                                int row, int lane, int sub, int c) {
    int start = g_rowstart[row];
    int end   = g_rowstart[row + 1];

    float4 a0 = make_float4(0.f, 0.f, 0.f, 0.f);
    for (int base = start; base < end; base += CHUNK) {
        int cnt = min(CHUNK, end - base);
        if (lane < cnt) se[lane] = __ldg(&g_epack[base + lane]);
        if (lane + 32 < cnt) se[lane + 32] = __ldg(&g_epack[base + lane + 32]);
        __syncwarp();
#pragma unroll 4
        for (int i = sub; i < cnt; i += 4) {
            float2 ev = se[i];
            float4 g = __ldg(&src[(size_t)__float_as_int(ev.x) * 8 + c]);
            a0.x = fmaf(ev.y, g.x, a0.x);
            a0.y = fmaf(ev.y, g.y, a0.y);
            a0.z = fmaf(ev.y, g.z, a0.z);
            a0.w = fmaf(ev.y, g.w, a0.w);
        }
        __syncwarp();
    }

#pragma unroll
    for (int off = 8; off < 32; off <<= 1) {
        a0.x += __shfl_xor_sync(0xFFFFFFFFu, a0.x, off);
        a0.y += __shfl_xor_sync(0xFFFFFFFFu, a0.y, off);
        a0.z += __shfl_xor_sync(0xFFFFFFFFu, a0.z, off);
        a0.w += __shfl_xor_sync(0xFFFFFFFFu, a0.w, off);
    }
    return a0;
}

// ---------------------------------------------------------------------------
// f16 fma helper: g = 8 packed halfs; accumulate v*g into lo/hi float4.
// ---------------------------------------------------------------------------
__device__ __forceinline__ void fma8h(float4 g, float v, float4& lo, float4& hi) {
    const __half2* h = reinterpret_cast<const __half2*>(&g);
    float2 p;
    p = __half22float2(h[0]); lo.x = fmaf(v, p.x, lo.x); lo.y = fmaf(v, p.y, lo.y);
    p = __half22float2(h[1]); lo.z = fmaf(v, p.x, lo.z); lo.w = fmaf(v, p.y, lo.w);
    p = __half22float2(h[2]); hi.x = fmaf(v, p.x, hi.x); hi.y = fmaf(v, p.y, hi.y);
    p = __half22float2(h[3]); hi.z = fmaf(v, p.x, hi.z); hi.w = fmaf(v, p.y, hi.w);
}

// ---------------------------------------------------------------------------
// Staged f16 warp row reduce, D=64: C=8 f4-chunks, SUBS=4, smem edge staging.
// ---------------------------------------------------------------------------
__device__ __forceinline__ void row_reduce64h(const float4* __restrict__ src,
                                              float2* __restrict__ se,
                                              int row, int lane, int sub, int c,
                                              float4& lo_out, float4& hi_out) {
    int start = g_rowstart[row];
    int end   = g_rowstart[row + 1];

    float4 l0 = make_float4(0.f, 0.f, 0.f, 0.f), h0 = l0;
    for (int base = start; base < end; base += CHUNK) {
        int cnt = min(CHUNK, end - base);
        if (lane < cnt) se[lane] = __ldg(&g_epack[base + lane]);
        if (lane + 32 < cnt) se[lane + 32] = __ldg(&g_epack[base + lane + 32]);
        __syncwarp();
#pragma unroll 4
        for (int i = sub; i < cnt; i += 4) {
            float2 ev = se[i];
            float4 g = __ldg(&src[(size_t)__float_as_int(ev.x) * 8 + c]);
            fma8h(g, ev.y, l0, h0);
        }
        __syncwarp();
    }

#pragma unroll
    for (int off = 8; off < 32; off <<= 1) {
        l0.x += __shfl_xor_sync(0xFFFFFFFFu, l0.x, off);
        l0.y += __shfl_xor_sync(0xFFFFFFFFu, l0.y, off);
        l0.z += __shfl_xor_sync(0xFFFFFFFFu, l0.z, off);
        l0.w += __shfl_xor_sync(0xFFFFFFFFu, l0.w, off);
        h0.x += __shfl_xor_sync(0xFFFFFFFFu, h0.x, off);
        h0.y += __shfl_xor_sync(0xFFFFFFFFu, h0.y, off);
        h0.z += __shfl_xor_sync(0xFFFFFFFFu, h0.z, off);
        h0.w += __shfl_xor_sync(0xFFFFFFFFu, h0.w, off);
    }
    lo_out = l0; hi_out = h0;
}

// ---------------------------------------------------------------------------
// Pass 1: SpMM D=32 f32, x -> bufA. One warp per row.
// ---------------------------------------------------------------------------
__global__ void spmm_gather32_kernel(const float* __restrict__ x) {
    __shared__ __align__(16) float2 sedge[8][CHUNK];
    const float4* __restrict__ src = reinterpret_cast<const float4*>(x);
    float4* dst = reinterpret_cast<float4*>(g_bufA);

    int warp_id = (blockIdx.x * blockDim.x + threadIdx.x) >> 5;
    if (warp_id >= N_NODES) return;
    int warp = (threadIdx.x >> 5);
    int lane = threadIdx.x & 31;
    int sub = lane >> 3, c = lane & 7;

    float4 acc = row_reduce32f(src, sedge[warp], warp_id, lane, sub, c);
    if (sub == 0) dst[(size_t)warp_id * 8 + c] = acc;
}

// ---------------------------------------------------------------------------
// Pass 2: fused SpMM(D=32 f32, bufA) + linear(32->64) + relu -> bufB (f16).
// 256 threads = 8 warps = 8 rows; warp-private srow + __syncwarp.
// ---------------------------------------------------------------------------
__global__ void spmm_linear32_kernel(const float* __restrict__ W,
                                     const float* __restrict__ b) {
    constexpr int WARPS = 8;
    __shared__ __align__(16) float sW[32][64];
    __shared__ __align__(16) float sbias[64];
    __shared__ __align__(16) float srow[WARPS][32];
    __shared__ __align__(16) float2 sedge[WARPS][CHUNK];

    const float4* __restrict__ src = reinterpret_cast<const float4*>(g_bufA);
    __half2* dst = reinterpret_cast<__half2*>(g_bufB);

    int tid = threadIdx.x;
    for (int k = tid; k < 32 * 64; k += 256) sW[k >> 6][k & 63] = W[k];
    if (tid < 64) sbias[tid] = b[tid];
    __syncthreads();

    int warp = tid >> 5, lane = tid & 31;
    int row = blockIdx.x * WARPS + warp;   // 100000 = 12500 * 8, exact
    int sub = lane >> 3, c = lane & 7;

    float4 acc = row_reduce32f(src, sedge[warp], row, lane, sub, c);
    if (sub == 0) reinterpret_cast<float4*>(srow[warp])[c] = acc;
    __syncwarp();

    const float2* sW2 = reinterpret_cast<const float2*>(&sW[0][0]);
    float2 o = reinterpret_cast<const float2*>(sbias)[lane];
#pragma unroll
    for (int k = 0; k < 32; k++) {
        float r = srow[warp][k];
        float2 w = sW2[k * 32 + lane];
        o.x = fmaf(r, w.x, o.x);
        o.y = fmaf(r, w.y, o.y);
    }
    o.x = fmaxf(o.x, 0.f);
    o.y = fmaxf(o.y, 0.f);
    dst[(size_t)row * 32 + lane] = __floats2half2_rn(o.x, o.y);
}

// ---------------------------------------------------------------------------
// Pass 3: SpMM D=64 f16, bufB -> bufA (f16). One warp per row, SUBS=4.
// ---------------------------------------------------------------------------
__global__ void spmm_gather64h_kernel() {
    __shared__ __align__(16) float2 sedge[8][CHUNK];
    const float4* __restrict__ src = reinterpret_cast<const float4*>(g_bufB);
    float4* dst = reinterpret_cast<float4*>(g_bufA);

    int warp_id = (blockIdx.x * blockDim.x + threadIdx.x) >> 5;
    if (warp_id >= N_NODES) return;
    int warp = (threadIdx.x >> 5);
    int lane = threadIdx.x & 31;
    int sub = lane >> 3, c = lane & 7;

    float4 lo, hi;
    row_reduce64h(src, sedge[warp], warp_id, lane, sub, c, lo, hi);
    if (sub == 0) {
        float4 pk;
        __half2* p = reinterpret_cast<__half2*>(&pk);
        p[0] = __floats2half2_rn(lo.x, lo.y);
        p[1] = __floats2half2_rn(lo.z, lo.w);
        p[2] = __floats2half2_rn(hi.x, hi.y);
        p[3] = __floats2half2_rn(hi.z, hi.w);
        dst[(size_t)warp_id * 8 + c] = pk;
    }
}

// ---------------------------------------------------------------------------
// Pass 4: fused SpMM(D=64 f16, bufA) + linear(64->64) + bias -> out (f32).
// ---------------------------------------------------------------------------
__global__ void spmm_linear64h_kernel(float* __restrict__ out,
                                      const float* __restrict__ W,
                                      const float* __restrict__ b) {
    constexpr int WARPS = 8;
    __shared__ __align__(16) float sW[64][64];
    __shared__ __align__(16) float sbias[64];
    __shared__ __align__(16) float srow[WARPS][64];
    __shared__ __align__(16) float2 sedge[WARPS][CHUNK];

    const float4* __restrict__ src = reinterpret_cast<const float4*>(g_bufA);

    int tid = threadIdx.x;
    for (int k = tid; k < 64 * 64; k += 256) sW[k >> 6][k & 63] = W[k];
    if (tid < 64) sbias[tid] = b[tid];
    __syncthreads();

    int warp = tid >> 5, lane = tid & 31;
    int row = blockIdx.x * WARPS + warp;   // exact
    int sub = lane >> 3, c = lane & 7;

    float4 lo, hi;
    row_reduce64h(src, sedge[warp], row, lane, sub, c, lo, hi);
    if (sub == 0) {
        float4* s4 = reinterpret_cast<float4*>(srow[warp]);
        s4[2 * c]     = lo;   // cols 8c .. 8c+3
        s4[2 * c + 1] = hi;   // cols 8c+4 .. 8c+7
    }
    __syncwarp();

    const float2* sW2 = reinterpret_cast<const float2*>(&sW[0][0]);
    float2 o = reinterpret_cast<const float2*>(sbias)[lane];
#pragma unroll
    for (int k = 0; k < 64; k++) {
        float r = srow[warp][k];
        float2 w = sW2[k * 32 + lane];
        o.x = fmaf(r, w.x, o.x);
        o.y = fmaf(r, w.y, o.y);
    }
    reinterpret_cast<float2*>(out)[(size_t)row * 32 + lane] = o;
}

// ---------------------------------------------------------------------------
// Launch sequence:
//   CSR build (5 kernels, shared by all 4 propagations)
//   bufA(f32,32) <- spmm(x)
//   bufB(f16,64) <- relu(spmm(bufA) @ W1 + b1)     (fused)
//   bufA(f16,64) <- spmm(bufB)
//   out(f32)     <- spmm(bufA) @ W2 + b2           (fused)
// ---------------------------------------------------------------------------
extern "C" void kernel_launch(void* const* d_in, const int* in_sizes, int n_in,
                              void* d_out, int out_size) {
    const float* x    = (const float*)d_in[0];
    const float* evl  = (const float*)d_in[1];
    const int*   erow = (const int*)  d_in[2];
    const int*   ecol = (const int*)  d_in[3];
    const float* W1   = (const float*)d_in[4];
    const float* b1   = (const float*)d_in[5];
    const float* W2   = (const float*)d_in[6];
    const float* b2   = (const float*)d_in[7];
    float* out = (float*)d_out;

    const int TPB = 256;
    int node_blocks = (N_NODES + TPB - 1) / TPB;
    int edge_blocks = (N_EDGES + TPB - 1) / TPB;
    int warp_blocks = (N_NODES * 32 + TPB - 1) / TPB;   // 12500
    int fused_blocks = N_NODES / 8;                      // 12500

    // --- CSR build ---
    zero_deg_kernel<<<node_blocks, TPB>>>();
    hist_kernel<<<edge_blocks, TPB>>>(erow);
    scan_local_kernel<<<SCAN_NB, SCAN_BS>>>();
    scan_add_kernel<<<node_blocks, TPB>>>();
    scatter_edges_kernel<<<edge_blocks, TPB>>>(erow, ecol, evl);

    // --- layer 1 ---
    spmm_gather32_kernel<<<warp_blocks, TPB>>>(x);
    spmm_linear32_kernel<<<fused_blocks, TPB>>>(W1, b1);

    // --- layer 2 (f16 features) ---
    spmm_gather64h_kernel<<<warp_blocks, TPB>>>();
    spmm_linear64h_kernel<<<fused_blocks, TPB>>>(out, W2, b2);
}